// round 2
// baseline (speedup 1.0000x reference)
#include <cuda_runtime.h>
#include <math.h>

// Problem shape (fixed by the dataset): B=8, S=2048, H=2048
#define M_DIM 16384   // B*S
#define H_DIM 2048    // hidden (K and N of GEMM1; both dims of new_w)

// Scratch for the norm reduction (allowed: __device__ globals, no allocation)
__device__ float g_partials[256];
__device__ float g_scale;

// ---------------------------------------------------------------------------
// GEMM1: combined[m,n] = sum_k x[m,k] * (Wf[n,k] + Wp[n,k]) + bias[n]
// 128x128 block tile, BK=16, 256 threads, 8x8 per-thread microtile,
// double-buffered smem with register prefetch.
// ---------------------------------------------------------------------------
__global__ __launch_bounds__(256) void gemm1_kernel(
    const float* __restrict__ A,   // x      [M_DIM, H_DIM]
    const float* __restrict__ Wf,  // fixed  [H_DIM, H_DIM]
    const float* __restrict__ Wp,  // plastic[H_DIM, H_DIM]
    const float* __restrict__ bias,
    float* __restrict__ C)         // combined [M_DIM, H_DIM]
{
    const int K = H_DIM, N = H_DIM;
    __shared__ float As[2][16][128];
    __shared__ float Bs[2][16][128];

    const int tid = threadIdx.x;
    const int tx  = tid & 15;        // 0..15 -> n microtile
    const int ty  = tid >> 4;        // 0..15 -> m microtile
    const int r0  = tid >> 2;        // 0..63 tile row for loads
    const int c4  = (tid & 3) << 2;  // 0,4,8,12 k-column for loads

    const float* Ap0  = A  + (size_t)(blockIdx.y * 128 + r0) * K + c4;
    const float* Ap1  = Ap0 + 64 * K;
    const float* Wfp0 = Wf + (size_t)(blockIdx.x * 128 + r0) * K + c4;
    const float* Wfp1 = Wfp0 + 64 * K;
    const float* Wpp0 = Wp + (size_t)(blockIdx.x * 128 + r0) * K + c4;
    const float* Wpp1 = Wpp0 + 64 * K;

    float4 pa0 = *(const float4*)Ap0;
    float4 pa1 = *(const float4*)Ap1;
    float4 pf0 = *(const float4*)Wfp0;
    float4 pf1 = *(const float4*)Wfp1;
    float4 pq0 = *(const float4*)Wpp0;
    float4 pq1 = *(const float4*)Wpp1;

#define G1_STORE(b)                                                                               \
    As[b][c4+0][r0]    = pa0.x; As[b][c4+1][r0]    = pa0.y;                                       \
    As[b][c4+2][r0]    = pa0.z; As[b][c4+3][r0]    = pa0.w;                                       \
    As[b][c4+0][r0+64] = pa1.x; As[b][c4+1][r0+64] = pa1.y;                                       \
    As[b][c4+2][r0+64] = pa1.z; As[b][c4+3][r0+64] = pa1.w;                                       \
    Bs[b][c4+0][r0]    = pf0.x + pq0.x; Bs[b][c4+1][r0]    = pf0.y + pq0.y;                       \
    Bs[b][c4+2][r0]    = pf0.z + pq0.z; Bs[b][c4+3][r0]    = pf0.w + pq0.w;                       \
    Bs[b][c4+0][r0+64] = pf1.x + pq1.x; Bs[b][c4+1][r0+64] = pf1.y + pq1.y;                       \
    Bs[b][c4+2][r0+64] = pf1.z + pq1.z; Bs[b][c4+3][r0+64] = pf1.w + pq1.w;

    float acc[8][8];
#pragma unroll
    for (int i = 0; i < 8; i++)
#pragma unroll
        for (int j = 0; j < 8; j++) acc[i][j] = 0.0f;

    int buf = 0;
    G1_STORE(0)
    __syncthreads();

    for (int kt = 16; kt < K + 16; kt += 16) {
        const bool more = (kt < K);
        if (more) {
            pa0 = *(const float4*)(Ap0 + kt);
            pa1 = *(const float4*)(Ap1 + kt);
            pf0 = *(const float4*)(Wfp0 + kt);
            pf1 = *(const float4*)(Wfp1 + kt);
            pq0 = *(const float4*)(Wpp0 + kt);
            pq1 = *(const float4*)(Wpp1 + kt);
        }
#pragma unroll
        for (int kk = 0; kk < 16; kk++) {
            float a[8], b[8];
            *(float4*)(a)     = *(const float4*)&As[buf][kk][ty * 8];
            *(float4*)(a + 4) = *(const float4*)&As[buf][kk][ty * 8 + 4];
            *(float4*)(b)     = *(const float4*)&Bs[buf][kk][tx * 8];
            *(float4*)(b + 4) = *(const float4*)&Bs[buf][kk][tx * 8 + 4];
#pragma unroll
            for (int i = 0; i < 8; i++)
#pragma unroll
                for (int j = 0; j < 8; j++) acc[i][j] += a[i] * b[j];
        }
        if (more) {
            const int nb = buf ^ 1;
            G1_STORE(nb)
            __syncthreads();
            buf = nb;
        }
    }
#undef G1_STORE

    const int m0 = blockIdx.y * 128 + ty * 8;
    const int n0 = blockIdx.x * 128 + tx * 8;
    float bv[8];
#pragma unroll
    for (int j = 0; j < 8; j++) bv[j] = bias[n0 + j];
#pragma unroll
    for (int i = 0; i < 8; i++) {
        float4 o0 = make_float4(acc[i][0] + bv[0], acc[i][1] + bv[1],
                                acc[i][2] + bv[2], acc[i][3] + bv[3]);
        float4 o1 = make_float4(acc[i][4] + bv[4], acc[i][5] + bv[5],
                                acc[i][6] + bv[6], acc[i][7] + bv[7]);
        *(float4*)&C[(size_t)(m0 + i) * N + n0]     = o0;
        *(float4*)&C[(size_t)(m0 + i) * N + n0 + 4] = o1;
    }
}

// ---------------------------------------------------------------------------
// GEMM2 (TN): outw[p,q] = Wp[p,q] + (rate*strength/R) * sum_m x[m,p]*combined[m,q]
// plus per-block sum-of-squares partial for the Frobenius norm.
// ---------------------------------------------------------------------------
__global__ __launch_bounds__(256) void gemm2_kernel(
    const float* __restrict__ X,    // x        [M_DIM, H_DIM]
    const float* __restrict__ Cm,   // combined [M_DIM, H_DIM]
    const float* __restrict__ Wp,   // plastic  [H_DIM, H_DIM]
    const float* __restrict__ pr,   // plasticity_rate [1]
    const float* __restrict__ hs,   // hebbian_strength [1]
    float* __restrict__ OutW)       // new_w (unnormalized) [H_DIM, H_DIM]
{
    const int Hn = H_DIM;
    const int R  = M_DIM;
    __shared__ float Xs[2][16][128];
    __shared__ float Cs[2][16][128];
    __shared__ float red[8];

    const int tid = threadIdx.x;
    const int tx  = tid & 15;
    const int ty  = tid >> 4;
    const int lr  = tid >> 5;        // 0..7 (m row within chunk)
    const int lc  = (tid & 31) << 2; // 0..124 column (float4)
    const int p0  = blockIdx.y * 128;
    const int q0  = blockIdx.x * 128;

    const float* Xp0 = X  + (size_t)lr * Hn + p0 + lc;
    const float* Xp1 = Xp0 + 8 * Hn;
    const float* Cp0 = Cm + (size_t)lr * Hn + q0 + lc;
    const float* Cp1 = Cp0 + 8 * Hn;

    float4 px0 = *(const float4*)Xp0;
    float4 px1 = *(const float4*)Xp1;
    float4 pc0 = *(const float4*)Cp0;
    float4 pc1 = *(const float4*)Cp1;

#define G2_STORE(b)                                          \
    *(float4*)&Xs[b][lr][lc]     = px0;                      \
    *(float4*)&Xs[b][lr + 8][lc] = px1;                      \
    *(float4*)&Cs[b][lr][lc]     = pc0;                      \
    *(float4*)&Cs[b][lr + 8][lc] = pc1;

    float acc[8][8];
#pragma unroll
    for (int i = 0; i < 8; i++)
#pragma unroll
        for (int j = 0; j < 8; j++) acc[i][j] = 0.0f;

    int buf = 0;
    G2_STORE(0)
    __syncthreads();

    for (int mt = 16; mt < R + 16; mt += 16) {
        const bool more = (mt < R);
        if (more) {
            const size_t off = (size_t)mt * Hn;
            px0 = *(const float4*)(Xp0 + off);
            px1 = *(const float4*)(Xp1 + off);
            pc0 = *(const float4*)(Cp0 + off);
            pc1 = *(const float4*)(Cp1 + off);
        }
#pragma unroll
        for (int mm = 0; mm < 16; mm++) {
            float a[8], b[8];
            *(float4*)(a)     = *(const float4*)&Xs[buf][mm][ty * 8];
            *(float4*)(a + 4) = *(const float4*)&Xs[buf][mm][ty * 8 + 4];
            *(float4*)(b)     = *(const float4*)&Cs[buf][mm][tx * 8];
            *(float4*)(b + 4) = *(const float4*)&Cs[buf][mm][tx * 8 + 4];
#pragma unroll
            for (int i = 0; i < 8; i++)
#pragma unroll
                for (int j = 0; j < 8; j++) acc[i][j] += a[i] * b[j];
        }
        if (more) {
            const int nb = buf ^ 1;
            G2_STORE(nb)
            __syncthreads();
            buf = nb;
        }
    }
#undef G2_STORE

    // Epilogue: new_w (unnormalized) + sum of squares
    const float factor = pr[0] * hs[0] * (1.0f / (float)R);
    float ssq = 0.0f;
#pragma unroll
    for (int i = 0; i < 8; i++) {
        const int p = p0 + ty * 8 + i;
        const size_t rowoff = (size_t)p * Hn + q0 + tx * 8;
#pragma unroll
        for (int j4 = 0; j4 < 2; j4++) {
            float4 w = *(const float4*)&Wp[rowoff + j4 * 4];
            float4 v;
            v.x = w.x + factor * acc[i][j4 * 4 + 0];
            v.y = w.y + factor * acc[i][j4 * 4 + 1];
            v.z = w.z + factor * acc[i][j4 * 4 + 2];
            v.w = w.w + factor * acc[i][j4 * 4 + 3];
            *(float4*)&OutW[rowoff + j4 * 4] = v;
            ssq += v.x * v.x + v.y * v.y + v.z * v.z + v.w * v.w;
        }
    }

    // Block reduce ssq -> g_partials[block]
#pragma unroll
    for (int o = 16; o; o >>= 1) ssq += __shfl_xor_sync(0xffffffffu, ssq, o);
    if ((tid & 31) == 0) red[tid >> 5] = ssq;
    __syncthreads();
    if (tid == 0) {
        float t = 0.0f;
#pragma unroll
        for (int w = 0; w < 8; w++) t += red[w];
        g_partials[blockIdx.y * gridDim.x + blockIdx.x] = t;
    }
}

// ---------------------------------------------------------------------------
// Norm finalize: reduce 256 partials, compute scale = (||W|| > 1) ? 1/||W|| : 1
// ---------------------------------------------------------------------------
__global__ void finalize_kernel() {
    const int tid = threadIdx.x;
    __shared__ float red[8];
    float v = g_partials[tid];
#pragma unroll
    for (int o = 16; o; o >>= 1) v += __shfl_xor_sync(0xffffffffu, v, o);
    if ((tid & 31) == 0) red[tid >> 5] = v;
    __syncthreads();
    if (tid == 0) {
        float t = 0.0f;
#pragma unroll
        for (int w = 0; w < 8; w++) t += red[w];
        const float n = sqrtf(t);
        g_scale = (n > 1.0f) ? (1.0f / n) : 1.0f;
    }
}

__global__ void scale_kernel(float* __restrict__ w) {
    const float s = g_scale;
    const int n4 = (H_DIM * H_DIM) / 4;
    float4* w4 = (float4*)w;
    for (int i = blockIdx.x * blockDim.x + threadIdx.x; i < n4;
         i += gridDim.x * blockDim.x) {
        float4 v = w4[i];
        v.x *= s; v.y *= s; v.z *= s; v.w *= s;
        w4[i] = v;
    }
}

// ---------------------------------------------------------------------------
// Launch: GEMM1 -> GEMM2(+partials) -> finalize -> scale. All on the capture
// stream, no sync, no allocation.
// Inputs (metadata order): x, plastic_weights, plasticity_rate, fixed_w,
//                          fixed_b, hebbian_strength
// Output: combined [16384,2048] followed by new_w [2048,2048]
// ---------------------------------------------------------------------------
extern "C" void kernel_launch(void* const* d_in, const int* in_sizes, int n_in,
                              void* d_out, int out_size)
{
    const float* x  = (const float*)d_in[0];
    const float* wp = (const float*)d_in[1];
    const float* pr = (const float*)d_in[2];
    const float* wf = (const float*)d_in[3];
    const float* fb = (const float*)d_in[4];
    const float* hs = (const float*)d_in[5];

    float* combined = (float*)d_out;
    float* outw     = combined + (size_t)M_DIM * H_DIM;

    dim3 g1(H_DIM / 128, M_DIM / 128);   // (16, 128)
    gemm1_kernel<<<g1, 256>>>(x, wf, wp, fb, combined);

    dim3 g2(H_DIM / 128, H_DIM / 128);   // (16, 16)
    gemm2_kernel<<<g2, 256>>>(x, combined, wp, pr, hs, outw);

    finalize_kernel<<<1, 256>>>();
    scale_kernel<<<2048, 256>>>(outw);
}

// round 3
// speedup vs baseline: 2.0157x; 2.0157x over previous
#include <cuda_runtime.h>
#include <stdint.h>
#include <math.h>

// Problem shape (fixed by the dataset): B=8, S=2048, H=2048
#define M_DIM 16384   // B*S
#define H_DIM 2048

__device__ float g_partials[256];
__device__ float g_scale;

// ---------------------------------------------------------------------------
// tf32 helpers
// ---------------------------------------------------------------------------
__device__ __forceinline__ uint32_t f2tf32(float f) {
    uint32_t r;
    asm("cvt.rna.tf32.f32 %0, %1;" : "=r"(r) : "f"(f));
    return r;
}
__device__ __forceinline__ uint4 tf32x4(float4 v) {
    uint4 r;
    r.x = f2tf32(v.x); r.y = f2tf32(v.y); r.z = f2tf32(v.z); r.w = f2tf32(v.w);
    return r;
}

#define MMA_TF32(d, a, b)                                                     \
    asm volatile(                                                             \
        "mma.sync.aligned.m16n8k8.row.col.f32.tf32.tf32.f32 "                 \
        "{%0,%1,%2,%3}, {%4,%5,%6,%7}, {%8,%9}, {%0,%1,%2,%3};\n"             \
        : "+f"(d[0]), "+f"(d[1]), "+f"(d[2]), "+f"(d[3])                      \
        : "r"(a[0]), "r"(a[1]), "r"(a[2]), "r"(a[3]), "r"(b[0]), "r"(b[1]))

// ---------------------------------------------------------------------------
// GEMM1 (tensor core): combined[m,n] = x[m,:] . (Wf[n,:]+Wp[n,:]) + bias[n]
// 128x128 tile, BK=16, 8 warps (2x4) of 64x32 warp tiles, m16n8k8 tf32 mma.
// Smem layout: [row][k], stride 20 (== 4 mod 32 -> conflict-free frag loads).
// ---------------------------------------------------------------------------
__global__ __launch_bounds__(256) void gemm1_tc(
    const float* __restrict__ A,   // x      [M_DIM, H_DIM]
    const float* __restrict__ Wf,  // fixed  [H_DIM, H_DIM]
    const float* __restrict__ Wp,  // plastic[H_DIM, H_DIM]
    const float* __restrict__ bias,
    float* __restrict__ C)         // combined [M_DIM, H_DIM]
{
    const int K = H_DIM, N = H_DIM;
    __shared__ uint32_t As[2][128][20];
    __shared__ uint32_t Bs[2][128][20];

    const int tid  = threadIdx.x;
    const int lane = tid & 31;
    const int warp = tid >> 5;
    const int g    = lane >> 2;       // 0..7
    const int t    = lane & 3;        // 0..3
    const int wm   = (warp >> 2) * 64;  // 0,64
    const int wn   = (warp & 3) * 32;   // 0,32,64,96
    const int r0   = tid >> 2;          // 0..63
    const int c4   = (tid & 3) << 2;    // 0,4,8,12

    const float* Ap0 = A  + (size_t)(blockIdx.y * 128 + r0) * K + c4;
    const float* Ap1 = Ap0 + 64 * (size_t)K;
    const float* Fp0 = Wf + (size_t)(blockIdx.x * 128 + r0) * K + c4;
    const float* Fp1 = Fp0 + 64 * (size_t)K;
    const float* Pp0 = Wp + (size_t)(blockIdx.x * 128 + r0) * K + c4;
    const float* Pp1 = Pp0 + 64 * (size_t)K;

    float4 pa0 = *(const float4*)Ap0;
    float4 pa1 = *(const float4*)Ap1;
    float4 pf0 = *(const float4*)Fp0;
    float4 pf1 = *(const float4*)Fp1;
    float4 pq0 = *(const float4*)Pp0;
    float4 pq1 = *(const float4*)Pp1;
    float4 pb0 = make_float4(pf0.x + pq0.x, pf0.y + pq0.y, pf0.z + pq0.z, pf0.w + pq0.w);
    float4 pb1 = make_float4(pf1.x + pq1.x, pf1.y + pq1.y, pf1.z + pq1.z, pf1.w + pq1.w);

#define G1_STORE(b)                                        \
    *(uint4*)&As[b][r0][c4]      = tf32x4(pa0);            \
    *(uint4*)&As[b][r0 + 64][c4] = tf32x4(pa1);            \
    *(uint4*)&Bs[b][r0][c4]      = tf32x4(pb0);            \
    *(uint4*)&Bs[b][r0 + 64][c4] = tf32x4(pb1);

    float acc[4][4][4];
#pragma unroll
    for (int mi = 0; mi < 4; mi++)
#pragma unroll
        for (int ni = 0; ni < 4; ni++)
#pragma unroll
            for (int c = 0; c < 4; c++) acc[mi][ni][c] = 0.0f;

    int buf = 0;
    G1_STORE(0)
    __syncthreads();

    for (int kt = 16; kt < K + 16; kt += 16) {
        const bool more = (kt < K);
        if (more) {
            pa0 = *(const float4*)(Ap0 + kt);
            pa1 = *(const float4*)(Ap1 + kt);
            pf0 = *(const float4*)(Fp0 + kt);
            pf1 = *(const float4*)(Fp1 + kt);
            pq0 = *(const float4*)(Pp0 + kt);
            pq1 = *(const float4*)(Pp1 + kt);
            pb0 = make_float4(pf0.x + pq0.x, pf0.y + pq0.y, pf0.z + pq0.z, pf0.w + pq0.w);
            pb1 = make_float4(pf1.x + pq1.x, pf1.y + pq1.y, pf1.z + pq1.z, pf1.w + pq1.w);
        }
#pragma unroll
        for (int ks = 0; ks < 16; ks += 8) {
            uint32_t af[4][4], bf[4][2];
#pragma unroll
            for (int mi = 0; mi < 4; mi++) {
                const int m = wm + mi * 16 + g;
                af[mi][0] = As[buf][m][ks + t];
                af[mi][1] = As[buf][m + 8][ks + t];
                af[mi][2] = As[buf][m][ks + t + 4];
                af[mi][3] = As[buf][m + 8][ks + t + 4];
            }
#pragma unroll
            for (int ni = 0; ni < 4; ni++) {
                const int n = wn + ni * 8 + g;
                bf[ni][0] = Bs[buf][n][ks + t];
                bf[ni][1] = Bs[buf][n][ks + t + 4];
            }
#pragma unroll
            for (int mi = 0; mi < 4; mi++)
#pragma unroll
                for (int ni = 0; ni < 4; ni++)
                    MMA_TF32(acc[mi][ni], af[mi], bf[ni]);
        }
        if (more) {
            const int nb = buf ^ 1;
            G1_STORE(nb)
            __syncthreads();
            buf = nb;
        }
    }
#undef G1_STORE

    // Epilogue: add bias, store fp32
    const int mbase = blockIdx.y * 128 + wm;
    const int nbase = blockIdx.x * 128 + wn;
#pragma unroll
    for (int ni = 0; ni < 4; ni++) {
        const int col = nbase + ni * 8 + 2 * t;
        const float bv0 = bias[col];
        const float bv1 = bias[col + 1];
#pragma unroll
        for (int mi = 0; mi < 4; mi++) {
            const int row0 = mbase + mi * 16 + g;
            float2 o0 = make_float2(acc[mi][ni][0] + bv0, acc[mi][ni][1] + bv1);
            float2 o1 = make_float2(acc[mi][ni][2] + bv0, acc[mi][ni][3] + bv1);
            *(float2*)&C[(size_t)row0 * N + col]       = o0;
            *(float2*)&C[(size_t)(row0 + 8) * N + col] = o1;
        }
    }
}

// ---------------------------------------------------------------------------
// GEMM2 (tensor core, TN): outw[p,q] = Wp[p,q] + f * sum_m x[m,p]*combined[m,q]
// Smem layout: [m-chunk][col], stride 136 (== 8 mod 32 -> conflict-free).
// Also emits per-block sum-of-squares partials for the Frobenius norm.
// ---------------------------------------------------------------------------
__global__ __launch_bounds__(256) void gemm2_tc(
    const float* __restrict__ X,    // x        [M_DIM, H_DIM]
    const float* __restrict__ Cm,   // combined [M_DIM, H_DIM]
    const float* __restrict__ Wp,   // plastic  [H_DIM, H_DIM]
    const float* __restrict__ pr,
    const float* __restrict__ hs,
    float* __restrict__ OutW)       // new_w (unnormalized) [H_DIM, H_DIM]
{
    const int Hn = H_DIM;
    const int R  = M_DIM;
    __shared__ uint32_t Xs[2][16][136];
    __shared__ uint32_t Cs[2][16][136];
    __shared__ float red[8];

    const int tid  = threadIdx.x;
    const int lane = tid & 31;
    const int warp = tid >> 5;
    const int g    = lane >> 2;
    const int t    = lane & 3;
    const int wm   = (warp >> 2) * 64;  // p-offset in tile
    const int wn   = (warp & 3) * 32;   // q-offset in tile
    const int lr   = tid >> 5;          // 0..7 (m row within chunk)
    const int lc   = (tid & 31) << 2;   // 0..124 column (float4)
    const int p0   = blockIdx.y * 128;
    const int q0   = blockIdx.x * 128;

    const float* Xp0 = X  + (size_t)lr * Hn + p0 + lc;
    const float* Xp1 = Xp0 + 8 * (size_t)Hn;
    const float* Cp0 = Cm + (size_t)lr * Hn + q0 + lc;
    const float* Cp1 = Cp0 + 8 * (size_t)Hn;

    float4 px0 = *(const float4*)Xp0;
    float4 px1 = *(const float4*)Xp1;
    float4 pc0 = *(const float4*)Cp0;
    float4 pc1 = *(const float4*)Cp1;

#define G2_STORE(b)                                   \
    *(uint4*)&Xs[b][lr][lc]     = tf32x4(px0);        \
    *(uint4*)&Xs[b][lr + 8][lc] = tf32x4(px1);        \
    *(uint4*)&Cs[b][lr][lc]     = tf32x4(pc0);        \
    *(uint4*)&Cs[b][lr + 8][lc] = tf32x4(pc1);

    float acc[4][4][4];
#pragma unroll
    for (int mi = 0; mi < 4; mi++)
#pragma unroll
        for (int ni = 0; ni < 4; ni++)
#pragma unroll
            for (int c = 0; c < 4; c++) acc[mi][ni][c] = 0.0f;

    int buf = 0;
    G2_STORE(0)
    __syncthreads();

    for (int mt = 16; mt < R + 16; mt += 16) {
        const bool more = (mt < R);
        if (more) {
            const size_t off = (size_t)mt * Hn;
            px0 = *(const float4*)(Xp0 + off);
            px1 = *(const float4*)(Xp1 + off);
            pc0 = *(const float4*)(Cp0 + off);
            pc1 = *(const float4*)(Cp1 + off);
        }
#pragma unroll
        for (int ks = 0; ks < 16; ks += 8) {
            uint32_t af[4][4], bf[4][2];
#pragma unroll
            for (int mi = 0; mi < 4; mi++) {
                const int p = wm + mi * 16 + g;
                af[mi][0] = Xs[buf][ks + t][p];
                af[mi][1] = Xs[buf][ks + t][p + 8];
                af[mi][2] = Xs[buf][ks + t + 4][p];
                af[mi][3] = Xs[buf][ks + t + 4][p + 8];
            }
#pragma unroll
            for (int ni = 0; ni < 4; ni++) {
                const int q = wn + ni * 8 + g;
                bf[ni][0] = Cs[buf][ks + t][q];
                bf[ni][1] = Cs[buf][ks + t + 4][q];
            }
#pragma unroll
            for (int mi = 0; mi < 4; mi++)
#pragma unroll
                for (int ni = 0; ni < 4; ni++)
                    MMA_TF32(acc[mi][ni], af[mi], bf[ni]);
        }
        if (more) {
            const int nb = buf ^ 1;
            G2_STORE(nb)
            __syncthreads();
            buf = nb;
        }
    }
#undef G2_STORE

    // Epilogue: new_w (unnormalized) + sum of squares
    const float factor = pr[0] * hs[0] * (1.0f / (float)R);
    float ssq = 0.0f;
#pragma unroll
    for (int ni = 0; ni < 4; ni++) {
        const int q = q0 + wn + ni * 8 + 2 * t;
#pragma unroll
        for (int mi = 0; mi < 4; mi++) {
            const int p = p0 + wm + mi * 16 + g;
            {
                float2 w = *(const float2*)&Wp[(size_t)p * Hn + q];
                float2 v = make_float2(w.x + factor * acc[mi][ni][0],
                                       w.y + factor * acc[mi][ni][1]);
                *(float2*)&OutW[(size_t)p * Hn + q] = v;
                ssq += v.x * v.x + v.y * v.y;
            }
            {
                float2 w = *(const float2*)&Wp[(size_t)(p + 8) * Hn + q];
                float2 v = make_float2(w.x + factor * acc[mi][ni][2],
                                       w.y + factor * acc[mi][ni][3]);
                *(float2*)&OutW[(size_t)(p + 8) * Hn + q] = v;
                ssq += v.x * v.x + v.y * v.y;
            }
        }
    }

#pragma unroll
    for (int o = 16; o; o >>= 1) ssq += __shfl_xor_sync(0xffffffffu, ssq, o);
    if (lane == 0) red[warp] = ssq;
    __syncthreads();
    if (tid == 0) {
        float tt = 0.0f;
#pragma unroll
        for (int w = 0; w < 8; w++) tt += red[w];
        g_partials[blockIdx.y * gridDim.x + blockIdx.x] = tt;
    }
}

// ---------------------------------------------------------------------------
// Norm finalize + conditional scale
// ---------------------------------------------------------------------------
__global__ void finalize_kernel() {
    const int tid = threadIdx.x;
    __shared__ float red[8];
    float v = g_partials[tid];
#pragma unroll
    for (int o = 16; o; o >>= 1) v += __shfl_xor_sync(0xffffffffu, v, o);
    if ((tid & 31) == 0) red[tid >> 5] = v;
    __syncthreads();
    if (tid == 0) {
        float t = 0.0f;
#pragma unroll
        for (int w = 0; w < 8; w++) t += red[w];
        const float n = sqrtf(t);
        g_scale = (n > 1.0f) ? (1.0f / n) : 1.0f;
    }
}

__global__ void scale_kernel(float* __restrict__ w) {
    const float s = g_scale;
    const int n4 = (H_DIM * H_DIM) / 4;
    float4* w4 = (float4*)w;
    for (int i = blockIdx.x * blockDim.x + threadIdx.x; i < n4;
         i += gridDim.x * blockDim.x) {
        float4 v = w4[i];
        v.x *= s; v.y *= s; v.z *= s; v.w *= s;
        w4[i] = v;
    }
}

// ---------------------------------------------------------------------------
// Inputs (metadata order): x, plastic_weights, plasticity_rate, fixed_w,
//                          fixed_b, hebbian_strength
// Output: combined [16384,2048] followed by new_w [2048,2048]
// ---------------------------------------------------------------------------
extern "C" void kernel_launch(void* const* d_in, const int* in_sizes, int n_in,
                              void* d_out, int out_size)
{
    const float* x  = (const float*)d_in[0];
    const float* wp = (const float*)d_in[1];
    const float* pr = (const float*)d_in[2];
    const float* wf = (const float*)d_in[3];
    const float* fb = (const float*)d_in[4];
    const float* hs = (const float*)d_in[5];

    float* combined = (float*)d_out;
    float* outw     = combined + (size_t)M_DIM * H_DIM;

    dim3 g1(H_DIM / 128, M_DIM / 128);   // (16, 128)
    gemm1_tc<<<g1, 256>>>(x, wf, wp, fb, combined);

    dim3 g2(H_DIM / 128, H_DIM / 128);   // (16, 16)
    gemm2_tc<<<g2, 256>>>(x, combined, wp, pr, hs, outw);

    finalize_kernel<<<1, 256>>>();
    scale_kernel<<<2048, 256>>>(outw);
}

// round 7
// speedup vs baseline: 2.8073x; 1.3928x over previous
#include <cuda_runtime.h>
#include <stdint.h>
#include <math.h>

// Problem shape (fixed by dataset): B=8, S=2048, H=2048
#define M_DIM 16384
#define H_DIM 2048

// Static device scratch (allowed; no runtime allocation)
__device__ float g_xr[(size_t)M_DIM * H_DIM];    // rna(x)            [m][h]
__device__ float g_xt[(size_t)H_DIM * M_DIM];    // rna(x)^T          [h][m]
__device__ float g_ct[(size_t)H_DIM * M_DIM];    // rna(combined)^T   [n][m]
__device__ float g_wsum[(size_t)H_DIM * H_DIM];  // rna(Wf + Wp)      [n][k]
__device__ float g_c2p[4][(size_t)H_DIM * H_DIM];// split-K partials of x^T @ combined
__device__ float g_partials[1024];
__device__ float g_scale;

// ---------------------------------------------------------------------------
// helpers
// ---------------------------------------------------------------------------
__device__ __forceinline__ uint32_t smem_u32(const void* p) {
    uint32_t a;
    asm("{ .reg .u64 t; cvta.to.shared.u64 t, %1; cvt.u32.u64 %0, t; }" : "=r"(a) : "l"(p));
    return a;
}
__device__ __forceinline__ uint32_t f2tf32(float f) {
    uint32_t r;
    asm("cvt.rna.tf32.f32 %0, %1;" : "=r"(r) : "f"(f));
    return r;
}
__device__ __forceinline__ uint4 tf32x4(float4 v) {
    uint4 r;
    r.x = f2tf32(v.x); r.y = f2tf32(v.y); r.z = f2tf32(v.z); r.w = f2tf32(v.w);
    return r;
}
__device__ __forceinline__ void cp16(uint32_t s, const void* g) {
    asm volatile("cp.async.cg.shared.global [%0], [%1], 16;" :: "r"(s), "l"(g) : "memory");
}
#define CP_COMMIT() asm volatile("cp.async.commit_group;" ::: "memory")
#define CP_WAIT2()  asm volatile("cp.async.wait_group 2;" ::: "memory")

__device__ __forceinline__ void ldsm4(uint32_t* r, uint32_t addr) {
    asm volatile("ldmatrix.sync.aligned.m8n8.x4.shared.b16 {%0,%1,%2,%3}, [%4];"
                 : "=r"(r[0]), "=r"(r[1]), "=r"(r[2]), "=r"(r[3]) : "r"(addr));
}

#define MMA_TF32(d, a0, a1, a2, a3, b0, b1)                                   \
    asm volatile(                                                             \
        "mma.sync.aligned.m16n8k8.row.col.f32.tf32.tf32.f32 "                 \
        "{%0,%1,%2,%3}, {%4,%5,%6,%7}, {%8,%9}, {%0,%1,%2,%3};\n"             \
        : "+f"((d)[0]), "+f"((d)[1]), "+f"((d)[2]), "+f"((d)[3])              \
        : "r"(a0), "r"(a1), "r"(a2), "r"(a3), "r"(b0), "r"(b1))

// Stage layout: 4 stages x 16KB. Within a stage:
//   A at +0:    4 quad-regions of 2KB; chunk(q, row) at q*2048 + ((row ^ 2q)*16)
//   B at +8192: same layout
#define STAGE_BYTES 16384
#define SMEM_G1 (128 * 132 * 4)   // 67584 (epilogue transpose buffer, > 64KB stages)
#define SMEM_G2 (4 * STAGE_BYTES) // 65536

// ---------------------------------------------------------------------------
// prep kernels
// ---------------------------------------------------------------------------
__global__ __launch_bounds__(256) void prep_w(const float* __restrict__ wf,
                                              const float* __restrict__ wpl) {
    int i4 = blockIdx.x * 256 + threadIdx.x;  // 1,048,576 float4
    float4 a = ((const float4*)wf)[i4];
    float4 b = ((const float4*)wpl)[i4];
    float4 s = make_float4(a.x + b.x, a.y + b.y, a.z + b.z, a.w + b.w);
    ((uint4*)g_wsum)[i4] = tf32x4(s);
}

// 32x32 tiles: write rna(x) (same layout) and rna(x)^T
__global__ __launch_bounds__(256) void prep_x(const float* __restrict__ x) {
    __shared__ float tsm[32][33];
    const int tx = threadIdx.x, ty = threadIdx.y;
    const int p0 = blockIdx.x * 32, m0 = blockIdx.y * 32;
#pragma unroll
    for (int i = 0; i < 4; i++) {
        const int m = m0 + ty + i * 8;
        float v = x[(size_t)m * H_DIM + p0 + tx];
        float r = __uint_as_float(f2tf32(v));
        g_xr[(size_t)m * H_DIM + p0 + tx] = r;
        tsm[ty + i * 8][tx] = r;
    }
    __syncthreads();
#pragma unroll
    for (int i = 0; i < 4; i++) {
        const int p = p0 + ty + i * 8;
        g_xt[(size_t)p * M_DIM + m0 + tx] = tsm[tx][ty + i * 8];
    }
}

// ---------------------------------------------------------------------------
// core mainloop pieces (shared by both GEMMs)
// ---------------------------------------------------------------------------
struct Frags {
    uint32_t rowA16[4];   // (wm + mi*16 + (lane&15)) * 16
    uint32_t rowB16[2];   // (wn + (2P + ((lane>>3)>>1))*8 + (lane&7)) * 16
    uint32_t qa, qb;      // lane>>4 ; (lane>>3)&1
};

__device__ __forceinline__ void init_frags(Frags& F, int lane, int wm, int wn) {
    const int G = lane >> 3;
#pragma unroll
    for (int mi = 0; mi < 4; mi++)
        F.rowA16[mi] = (uint32_t)(wm + mi * 16 + (lane & 15)) * 16u;
#pragma unroll
    for (int P = 0; P < 2; P++)
        F.rowB16[P] = (uint32_t)(wn + (2 * P + (G >> 1)) * 8 + (lane & 7)) * 16u;
    F.qa = (uint32_t)(lane >> 4);
    F.qb = (uint32_t)(G & 1);
}

__device__ __forceinline__ void compute_stage(const Frags& F, uint32_t stg,
                                              float acc[4][4][4]) {
#pragma unroll
    for (int ks8 = 0; ks8 < 2; ks8++) {
        const uint32_t aq = (uint32_t)(ks8 * 2) + F.qa;
        const uint32_t bq = (uint32_t)(ks8 * 2) + F.qb;
        uint32_t af[4][4], bf[2][4];
#pragma unroll
        for (int mi = 0; mi < 4; mi++)
            ldsm4(af[mi], stg + aq * 2048u + (F.rowA16[mi] ^ (aq << 5)));
#pragma unroll
        for (int P = 0; P < 2; P++)
            ldsm4(bf[P], stg + 8192u + bq * 2048u + (F.rowB16[P] ^ (bq << 5)));
#pragma unroll
        for (int mi = 0; mi < 4; mi++)
#pragma unroll
            for (int P = 0; P < 2; P++) {
                MMA_TF32(acc[mi][2 * P],     af[mi][0], af[mi][1], af[mi][2], af[mi][3],
                         bf[P][0], bf[P][1]);
                MMA_TF32(acc[mi][2 * P + 1], af[mi][0], af[mi][1], af[mi][2], af[mi][3],
                         bf[P][2], bf[P][3]);
            }
    }
}

// ---------------------------------------------------------------------------
// GEMM1: combined[m,n] = g_xr[m,:] . g_wsum[n,:] + bias[n]
// Writes: C (fp32, [m][n]) and g_ct (rna(combined)^T, [n][m])
// ---------------------------------------------------------------------------
__global__ __launch_bounds__(256, 2) void gemm1_k(
    const float* __restrict__ bias, float* __restrict__ C)
{
    extern __shared__ char sm[];
    const uint32_t sbase = smem_u32(sm);
    const int tid = threadIdx.x, lane = tid & 31, warp = tid >> 5;
    const int g = lane >> 2, t = lane & 3;
    const int wm = (warp >> 2) * 64, wn = (warp & 3) * 32;
    const int m0 = blockIdx.y * 128, n0 = blockIdx.x * 128;

    // loader
    const int lq = tid & 3, lr = tid >> 2;  // lr 0..63
    const float* gA0 = g_xr   + (size_t)(m0 + lr) * H_DIM + lq * 4;
    const float* gA1 = gA0 + (size_t)64 * H_DIM;
    const float* gB0 = g_wsum + (size_t)(n0 + lr) * H_DIM + lq * 4;
    const float* gB1 = gB0 + (size_t)64 * H_DIM;
    const uint32_t sA0 = sbase + (uint32_t)lq * 2048u + (uint32_t)((lr ^ (2 * lq)) * 16);

    Frags F;
    init_frags(F, lane, wm, wn);

    float acc[4][4][4];
#pragma unroll
    for (int mi = 0; mi < 4; mi++)
#pragma unroll
        for (int ni = 0; ni < 4; ni++)
#pragma unroll
            for (int c = 0; c < 4; c++) acc[mi][ni][c] = 0.0f;

#define G1_ISSUE(kt) do {                                                  \
        const uint32_t st = (uint32_t)((kt) & 3) * STAGE_BYTES;            \
        const int ko = (kt) * 16;                                          \
        cp16(sA0 + st,          gA0 + ko);                                 \
        cp16(sA0 + st + 1024u,  gA1 + ko);                                 \
        cp16(sA0 + st + 8192u,  gB0 + ko);                                 \
        cp16(sA0 + st + 9216u,  gB1 + ko);                                 \
    } while (0)

    G1_ISSUE(0); CP_COMMIT();
    G1_ISSUE(1); CP_COMMIT();
    G1_ISSUE(2); CP_COMMIT();

    const int KT = H_DIM / 16;  // 128
    for (int kt = 0; kt < KT; kt++) {
        CP_WAIT2();
        __syncthreads();
        if (kt + 3 < KT) { G1_ISSUE(kt + 3); }
        CP_COMMIT();
        compute_stage(F, sbase + (uint32_t)(kt & 3) * STAGE_BYTES, acc);
    }
#undef G1_ISSUE

    __syncthreads();  // stages free -> reuse smem for transpose

    // Epilogue: add bias; store combined; stash rounded values transposed in smem
    float* Csm = (float*)sm;  // [n 128][m 132] words (pad 4 -> conflict-free)
#pragma unroll
    for (int ni = 0; ni < 4; ni++) {
        const int n = wn + ni * 8 + 2 * t;
        const float2 bv = *(const float2*)&bias[n0 + n];
#pragma unroll
        for (int mi = 0; mi < 4; mi++) {
            const int m = wm + mi * 16 + g;
            float v0 = acc[mi][ni][0] + bv.x, v1 = acc[mi][ni][1] + bv.y;
            float v2 = acc[mi][ni][2] + bv.x, v3 = acc[mi][ni][3] + bv.y;
            *(float2*)&C[(size_t)(m0 + m) * H_DIM + n0 + n]     = make_float2(v0, v1);
            *(float2*)&C[(size_t)(m0 + m + 8) * H_DIM + n0 + n] = make_float2(v2, v3);
            Csm[n * 132 + m]           = __uint_as_float(f2tf32(v0));
            Csm[(n + 1) * 132 + m]     = __uint_as_float(f2tf32(v1));
            Csm[n * 132 + m + 8]       = __uint_as_float(f2tf32(v2));
            Csm[(n + 1) * 132 + m + 8] = __uint_as_float(f2tf32(v3));
        }
    }
    __syncthreads();
    // Coalesced store of the transposed tile
    for (int idx = tid; idx < 128 * 32; idx += 256) {
        const int nrow = idx >> 5, mq = idx & 31;
        float4 v = *(const float4*)&Csm[nrow * 132 + mq * 4];
        *(float4*)&g_ct[(size_t)(n0 + nrow) * M_DIM + m0 + mq * 4] = v;
    }
}

// ---------------------------------------------------------------------------
// GEMM2 (split-K=4): g_c2p[sp][p,q] = sum_{m in split} g_xt[p,m]*g_ct[q,m]
// ---------------------------------------------------------------------------
__global__ __launch_bounds__(256, 2) void gemm2_k()
{
    extern __shared__ char sm[];
    const uint32_t sbase = smem_u32(sm);
    const int tid = threadIdx.x, lane = tid & 31, warp = tid >> 5;
    const int g = lane >> 2, t = lane & 3;
    const int wm = (warp >> 2) * 64, wn = (warp & 3) * 32;
    const int p0 = blockIdx.y * 128, q0 = blockIdx.x * 128;
    const int sp = blockIdx.z;
    const int mbase = sp * (M_DIM / 4);

    const int lq = tid & 3, lr = tid >> 2;
    const float* gA0 = g_xt + (size_t)(p0 + lr) * M_DIM + mbase + lq * 4;
    const float* gA1 = gA0 + (size_t)64 * M_DIM;
    const float* gB0 = g_ct + (size_t)(q0 + lr) * M_DIM + mbase + lq * 4;
    const float* gB1 = gB0 + (size_t)64 * M_DIM;
    const uint32_t sA0 = sbase + (uint32_t)lq * 2048u + (uint32_t)((lr ^ (2 * lq)) * 16);

    Frags F;
    init_frags(F, lane, wm, wn);

    float acc[4][4][4];
#pragma unroll
    for (int mi = 0; mi < 4; mi++)
#pragma unroll
        for (int ni = 0; ni < 4; ni++)
#pragma unroll
            for (int c = 0; c < 4; c++) acc[mi][ni][c] = 0.0f;

#define G2_ISSUE(kt) do {                                                  \
        const uint32_t st = (uint32_t)((kt) & 3) * STAGE_BYTES;            \
        const int ko = (kt) * 16;                                          \
        cp16(sA0 + st,          gA0 + ko);                                 \
        cp16(sA0 + st + 1024u,  gA1 + ko);                                 \
        cp16(sA0 + st + 8192u,  gB0 + ko);                                 \
        cp16(sA0 + st + 9216u,  gB1 + ko);                                 \
    } while (0)

    G2_ISSUE(0); CP_COMMIT();
    G2_ISSUE(1); CP_COMMIT();
    G2_ISSUE(2); CP_COMMIT();

    const int KT = (M_DIM / 4) / 16;  // 256
    for (int kt = 0; kt < KT; kt++) {
        CP_WAIT2();
        __syncthreads();
        if (kt + 3 < KT) { G2_ISSUE(kt + 3); }
        CP_COMMIT();
        compute_stage(F, sbase + (uint32_t)(kt & 3) * STAGE_BYTES, acc);
    }
#undef G2_ISSUE

    float* dst = g_c2p[sp];
#pragma unroll
    for (int ni = 0; ni < 4; ni++) {
        const int q = q0 + wn + ni * 8 + 2 * t;
#pragma unroll
        for (int mi = 0; mi < 4; mi++) {
            const int p = p0 + wm + mi * 16 + g;
            *(float2*)&dst[(size_t)p * H_DIM + q]       = make_float2(acc[mi][ni][0], acc[mi][ni][1]);
            *(float2*)&dst[(size_t)(p + 8) * H_DIM + q] = make_float2(acc[mi][ni][2], acc[mi][ni][3]);
        }
    }
}

// ---------------------------------------------------------------------------
// Combine split-K partials; Frobenius norm; conditional scale
// ---------------------------------------------------------------------------
__global__ __launch_bounds__(256) void combine_kernel(
    const float* __restrict__ wpl, const float* __restrict__ pr,
    const float* __restrict__ hs, float* __restrict__ outw)
{
    __shared__ float red[8];
    const int tid = threadIdx.x;
    const float f = pr[0] * hs[0] * (1.0f / (float)M_DIM);
    float ssq = 0.0f;
#pragma unroll
    for (int r = 0; r < 4; r++) {
        const int i4 = blockIdx.x * 1024 + r * 256 + tid;
        float4 a = ((const float4*)g_c2p[0])[i4];
        float4 b = ((const float4*)g_c2p[1])[i4];
        float4 c = ((const float4*)g_c2p[2])[i4];
        float4 d = ((const float4*)g_c2p[3])[i4];
        float4 w = ((const float4*)wpl)[i4];
        float4 v;
        v.x = w.x + f * (a.x + b.x + c.x + d.x);
        v.y = w.y + f * (a.y + b.y + c.y + d.y);
        v.z = w.z + f * (a.z + b.z + c.z + d.z);
        v.w = w.w + f * (a.w + b.w + c.w + d.w);
        ((float4*)outw)[i4] = v;
        ssq += v.x * v.x + v.y * v.y + v.z * v.z + v.w * v.w;
    }
#pragma unroll
    for (int o = 16; o; o >>= 1) ssq += __shfl_xor_sync(0xffffffffu, ssq, o);
    if ((tid & 31) == 0) red[tid >> 5] = ssq;
    __syncthreads();
    if (tid == 0) {
        float s = 0.0f;
#pragma unroll
        for (int w = 0; w < 8; w++) s += red[w];
        g_partials[blockIdx.x] = s;
    }
}

__global__ void finalize_kernel() {
    const int tid = threadIdx.x;
    __shared__ float red[8];
    float v = g_partials[tid] + g_partials[tid + 256] +
              g_partials[tid + 512] + g_partials[tid + 768];
#pragma unroll
    for (int o = 16; o; o >>= 1) v += __shfl_xor_sync(0xffffffffu, v, o);
    if ((tid & 31) == 0) red[tid >> 5] = v;
    __syncthreads();
    if (tid == 0) {
        float s = 0.0f;
#pragma unroll
        for (int w = 0; w < 8; w++) s += red[w];
        const float n = sqrtf(s);
        g_scale = (n > 1.0f) ? (1.0f / n) : 1.0f;
    }
}

__global__ void scale_kernel(float* __restrict__ w) {
    const float s = g_scale;
    const int n4 = (H_DIM * H_DIM) / 4;
    float4* w4 = (float4*)w;
    for (int i = blockIdx.x * blockDim.x + threadIdx.x; i < n4;
         i += gridDim.x * blockDim.x) {
        float4 v = w4[i];
        v.x *= s; v.y *= s; v.z *= s; v.w *= s;
        w4[i] = v;
    }
}

// ---------------------------------------------------------------------------
// Inputs: x, plastic_weights, plasticity_rate, fixed_w, fixed_b, hebbian_strength
// Output: combined [16384,2048] ++ new_w [2048,2048]
// ---------------------------------------------------------------------------
extern "C" void kernel_launch(void* const* d_in, const int* in_sizes, int n_in,
                              void* d_out, int out_size)
{
    const float* x  = (const float*)d_in[0];
    const float* wp = (const float*)d_in[1];
    const float* pr = (const float*)d_in[2];
    const float* wf = (const float*)d_in[3];
    const float* fb = (const float*)d_in[4];
    const float* hs = (const float*)d_in[5];

    float* combined = (float*)d_out;
    float* outw     = combined + (size_t)M_DIM * H_DIM;

    cudaFuncSetAttribute(gemm1_k, cudaFuncAttributeMaxDynamicSharedMemorySize, SMEM_G1);
    cudaFuncSetAttribute(gemm2_k, cudaFuncAttributeMaxDynamicSharedMemorySize, SMEM_G2);

    prep_w<<<4096, 256>>>(wf, wp);
    prep_x<<<dim3(H_DIM / 32, M_DIM / 32), dim3(32, 8)>>>(x);

    gemm1_k<<<dim3(16, 128), 256, SMEM_G1>>>(fb, combined);
    gemm2_k<<<dim3(16, 16, 4), 256, SMEM_G2>>>();

    combine_kernel<<<1024, 256>>>(wp, pr, hs, outw);
    finalize_kernel<<<1, 256>>>();
    scale_kernel<<<2048, 256>>>(outw);
}